// round 8
// baseline (speedup 1.0000x reference)
#include <cuda_runtime.h>

#define NPIX 65536
#define CIN 128
#define NH 4
#define NT 4
#define OD 512            // NH * 128 folded dimension
#define TILE 64           // pixels per block
#define NTHREADS 512
#define ZST 68            // zsT row stride (padded)
#define UST 516           // Us row stride (padded, multiple of 4)
#define SMEM_FLOATS (CIN*ZST + TILE*UST + 16*OD)
#define SCALE 0.08838834764831845f   // 1/sqrt(128)

// Folded weights (precomputed each call; no caching)
__device__ float g_Mcat[CIN*OD];   // [c1][o], o = h*128 + c2 : Wq_h^T Wk_h
__device__ float g_Pcat[OD*CIN];   // [o][d]                  : Wo_h Wv_h

__global__ void precompute_MP(const float* __restrict__ Wq, const float* __restrict__ Wk,
                              const float* __restrict__ Wv, const float* __restrict__ Wo) {
    int idx = blockIdx.x * blockDim.x + threadIdx.x;
    if (idx >= CIN*OD) return;
    // Mcat[c1*512 + (h*128+c2)] = sum_cc Wq[(cc*4+h), c1] * Wk[(cc*4+h), c2]
    {
        int c1 = idx >> 9;
        int o  = idx & (OD-1);
        int h = o >> 7, c2 = o & 127;
        float s = 0.f;
        #pragma unroll 4
        for (int cc = 0; cc < 64; cc++) {
            int row = (cc*4 + h) * CIN;
            s += Wq[row + c1] * Wk[row + c2];
        }
        g_Mcat[idx] = s;
    }
    // Pcat[(h*128+c2)*128 + d] = sum_cc Wo[d, cc*4+h] * Wv[(cc*4+h), c2]
    {
        int o = idx >> 7;
        int d = idx & 127;
        int h = o >> 7, c2 = o & 127;
        float s = 0.f;
        #pragma unroll 4
        for (int cc = 0; cc < 64; cc++) {
            int ch = cc*4 + h;
            s += Wo[d*256 + ch] * Wv[ch*CIN + c2];
        }
        g_Pcat[idx] = s;
    }
}

__device__ __forceinline__ unsigned long long pack2(float x) {
    unsigned long long r;
    asm("mov.b64 %0, {%1, %1};" : "=l"(r) : "f"(x));
    return r;
}
__device__ __forceinline__ void fma2(unsigned long long &d, unsigned long long a, unsigned long long b) {
    asm("fma.rn.f32x2 %0, %1, %2, %0;" : "+l"(d) : "l"(a), "l"(b));
}

__global__ void __launch_bounds__(NTHREADS, 1)
attn_fused(const float* __restrict__ z2d, const float* __restrict__ t2d,
           const float* __restrict__ bo, float* __restrict__ out)
{
    extern __shared__ float sm[];
    float* zsT = sm;                       // [CIN][ZST]  transposed z tile
    float* Us  = sm + CIN*ZST;             // [TILE][UST] U, later zbar (in place)
    float* buf = Us + TILE*UST;            // [16][512] M chunk / [32][128] P chunk

    const int tid = threadIdx.x;
    const int p0  = blockIdx.x * TILE;

    // ---- load z tile, transposed ----
    {
        const float* zsrc = z2d + (long)p0 * CIN;
        #pragma unroll
        for (int i = 0; i < TILE*CIN/NTHREADS; i++) {
            int idx = tid + i*NTHREADS;
            int px = idx >> 7, c = idx & 127;
            zsT[c*ZST + px] = zsrc[idx];
        }
    }
    __syncthreads();

    const int pixgrp = tid >> 6;   // 0..7 -> 8 pixels each
    const int lsub   = tid & 63;   // column-pair owner

    // ---- phase 1: U[64][512] = Z[64][128] @ Mcat[128][512] ----
    unsigned long long acc[32];    // [px 8][head 4] f32x2 pairs at o = k*128 + 2*lsub
    #pragma unroll
    for (int i = 0; i < 32; i++) acc[i] = 0ull;

    for (int c0 = 0; c0 < CIN; c0 += 16) {
        __syncthreads();
        const float* msrc = g_Mcat + c0*OD;
        #pragma unroll
        for (int i = 0; i < 16; i++)
            buf[tid + i*NTHREADS] = msrc[tid + i*NTHREADS];
        __syncthreads();
        #pragma unroll
        for (int kk = 0; kk < 16; kk++) {
            const float* zrow = zsT + (c0+kk)*ZST + pixgrp*8;
            float4 za  = *(const float4*)(zrow);
            float4 zbv = *(const float4*)(zrow + 4);
            unsigned long long zz[8];
            zz[0]=pack2(za.x);  zz[1]=pack2(za.y);  zz[2]=pack2(za.z);  zz[3]=pack2(za.w);
            zz[4]=pack2(zbv.x); zz[5]=pack2(zbv.y); zz[6]=pack2(zbv.z); zz[7]=pack2(zbv.w);
            const float* mrow = buf + kk*OD + 2*lsub;
            #pragma unroll
            for (int k = 0; k < 4; k++) {
                unsigned long long mv = *(const unsigned long long*)(mrow + k*128);
                #pragma unroll
                for (int px = 0; px < 8; px++)
                    fma2(acc[px*4 + k], zz[px], mv);
            }
        }
    }
    #pragma unroll
    for (int px = 0; px < 8; px++) {
        float* urow = Us + (pixgrp*8 + px)*UST + 2*lsub;
        #pragma unroll
        for (int k = 0; k < 4; k++)
            *(unsigned long long*)(urow + k*128) = acc[px*4 + k];
    }
    __syncthreads();

    // ---- phase 2: scores (U . z_t), softmax over t, zbar -> Us (in place) ----
    {
        const int pix = tid >> 3;     // 0..63
        const int sub = tid & 7;      // 8 threads per pixel, within one warp
        const int cb  = sub * 16;
        const float* zt0 = t2d + (long)(p0 + pix) * CIN + cb;

        float s[NT][NH];
        #pragma unroll
        for (int t = 0; t < NT; t++) {
            const float* ztp = zt0 + (long)t * NPIX * CIN;
            float4 zl[4];
            #pragma unroll
            for (int q4 = 0; q4 < 4; q4++) zl[q4] = *(const float4*)(ztp + q4*4);
            #pragma unroll
            for (int h = 0; h < NH; h++) {
                const float* urow = Us + pix*UST + h*128 + cb;
                float p = 0.f;
                #pragma unroll
                for (int q4 = 0; q4 < 4; q4++) {
                    float4 u = *(const float4*)(urow + q4*4);
                    p += u.x*zl[q4].x + u.y*zl[q4].y + u.z*zl[q4].z + u.w*zl[q4].w;
                }
                p += __shfl_xor_sync(0xffffffffu, p, 1);
                p += __shfl_xor_sync(0xffffffffu, p, 2);
                p += __shfl_xor_sync(0xffffffffu, p, 4);
                s[t][h] = p * SCALE;
            }
        }
        float w[NT][NH];
        #pragma unroll
        for (int h = 0; h < NH; h++) {
            float m = fmaxf(fmaxf(s[0][h], s[1][h]), fmaxf(s[2][h], s[3][h]));
            float e0 = __expf(s[0][h]-m), e1 = __expf(s[1][h]-m);
            float e2 = __expf(s[2][h]-m), e3 = __expf(s[3][h]-m);
            float inv = 1.f / (e0+e1+e2+e3);
            w[0][h]=e0*inv; w[1][h]=e1*inv; w[2][h]=e2*inv; w[3][h]=e3*inv;
        }
        float zb[NH][16];
        #pragma unroll
        for (int h = 0; h < NH; h++)
            #pragma unroll
            for (int q = 0; q < 16; q++) zb[h][q] = 0.f;
        #pragma unroll
        for (int t = 0; t < NT; t++) {
            const float* ztp = zt0 + (long)t * NPIX * CIN;   // L1/L2 hit (just read)
            float4 zl[4];
            #pragma unroll
            for (int q4 = 0; q4 < 4; q4++) zl[q4] = *(const float4*)(ztp + q4*4);
            #pragma unroll
            for (int h = 0; h < NH; h++) {
                float wv = w[t][h];
                #pragma unroll
                for (int q4 = 0; q4 < 4; q4++) {
                    zb[h][q4*4+0] = fmaf(wv, zl[q4].x, zb[h][q4*4+0]);
                    zb[h][q4*4+1] = fmaf(wv, zl[q4].y, zb[h][q4*4+1]);
                    zb[h][q4*4+2] = fmaf(wv, zl[q4].z, zb[h][q4*4+2]);
                    zb[h][q4*4+3] = fmaf(wv, zl[q4].w, zb[h][q4*4+3]);
                }
            }
        }
        // overwrite own U slots with zbar (disjoint per-thread, no race)
        #pragma unroll
        for (int h = 0; h < NH; h++) {
            float* urow = Us + pix*UST + h*128 + cb;
            #pragma unroll
            for (int q4 = 0; q4 < 4; q4++)
                *(float4*)(urow + q4*4) = make_float4(zb[h][q4*4+0], zb[h][q4*4+1],
                                                      zb[h][q4*4+2], zb[h][q4*4+3]);
        }
    }
    __syncthreads();

    // ---- phase 3: out[64][128] = zbar[64][512] @ Pcat[512][128] + bo ----
    {
        unsigned long long oacc[8];
        unsigned long long bo2 = *(const unsigned long long*)(bo + 2*lsub);
        #pragma unroll
        for (int px = 0; px < 8; px++) oacc[px] = bo2;

        for (int o0 = 0; o0 < OD; o0 += 32) {
            __syncthreads();
            const float* psrc = g_Pcat + o0*CIN;
            #pragma unroll
            for (int i = 0; i < 8; i++)
                buf[tid + i*NTHREADS] = psrc[tid + i*NTHREADS];
            __syncthreads();
            #pragma unroll
            for (int og = 0; og < 8; og++) {
                unsigned long long pm[4];
                #pragma unroll
                for (int r = 0; r < 4; r++)
                    pm[r] = *(const unsigned long long*)(buf + (og*4+r)*CIN + 2*lsub);
                #pragma unroll
                for (int px = 0; px < 8; px++) {
                    const float4 zq = *(const float4*)(Us + (pixgrp*8+px)*UST + o0 + og*4);
                    fma2(oacc[px], pack2(zq.x), pm[0]);
                    fma2(oacc[px], pack2(zq.y), pm[1]);
                    fma2(oacc[px], pack2(zq.z), pm[2]);
                    fma2(oacc[px], pack2(zq.w), pm[3]);
                }
            }
        }
        #pragma unroll
        for (int px = 0; px < 8; px++) {
            long p = p0 + pixgrp*8 + px;
            *(unsigned long long*)(out + p*CIN + 2*lsub) = oacc[px];
        }
    }
}

extern "C" void kernel_launch(void* const* d_in, const int* in_sizes, int n_in,
                              void* d_out, int out_size) {
    const float* z2d = (const float*)d_in[0];
    const float* t2d = (const float*)d_in[1];
    const float* Wq  = (const float*)d_in[2];
    const float* Wk  = (const float*)d_in[3];
    const float* Wv  = (const float*)d_in[4];
    const float* Wo  = (const float*)d_in[5];
    const float* bo  = (const float*)d_in[6];
    float* out = (float*)d_out;

    precompute_MP<<<(CIN*OD + 255)/256, 256>>>(Wq, Wk, Wv, Wo);

    cudaFuncSetAttribute(attn_fused, cudaFuncAttributeMaxDynamicSharedMemorySize,
                         SMEM_FLOATS * (int)sizeof(float));
    attn_fused<<<NPIX/TILE, NTHREADS, SMEM_FLOATS * sizeof(float)>>>(z2d, t2d, bo, out);
}

// round 9
// speedup vs baseline: 1.1794x; 1.1794x over previous
#include <cuda_runtime.h>

#define NPIX 65536
#define CIN 128
#define NH 4
#define NT 4
#define OD 512            // NH * 128 folded dimension
#define TILE 64           // pixels per block
#define NTHREADS 512
#define ZST 68            // zsT row stride (padded)
#define UST 516           // Us row stride (padded, multiple of 4)
#define CHUNK_FLOATS 4096 // 8 rows x 512 (phase 1) / 32 rows x 128 (phase 3)
#define SMEM_FLOATS (CIN*ZST + TILE*UST + 2*CHUNK_FLOATS)
#define SCALE 0.08838834764831845f   // 1/sqrt(128)

// Folded weights (precomputed each call; no caching)
__device__ float g_Mcat[CIN*OD];   // [c1][o], o = h*128 + c2 : Wq_h^T Wk_h
__device__ float g_Pcat[OD*CIN];   // [o][d]                  : Wo_h Wv_h

__global__ void precompute_MP(const float* __restrict__ Wq, const float* __restrict__ Wk,
                              const float* __restrict__ Wv, const float* __restrict__ Wo) {
    int idx = blockIdx.x * blockDim.x + threadIdx.x;
    if (idx >= CIN*OD) return;
    {
        int c1 = idx >> 9;
        int o  = idx & (OD-1);
        int h = o >> 7, c2 = o & 127;
        float s = 0.f;
        #pragma unroll 4
        for (int cc = 0; cc < 64; cc++) {
            int row = (cc*4 + h) * CIN;
            s += Wq[row + c1] * Wk[row + c2];
        }
        g_Mcat[idx] = s;
    }
    {
        int o = idx >> 7;
        int d = idx & 127;
        int h = o >> 7, c2 = o & 127;
        float s = 0.f;
        #pragma unroll 4
        for (int cc = 0; cc < 64; cc++) {
            int ch = cc*4 + h;
            s += Wo[d*256 + ch] * Wv[ch*CIN + c2];
        }
        g_Pcat[idx] = s;
    }
}

__device__ __forceinline__ unsigned long long pack2(float x) {
    unsigned long long r;
    asm("mov.b64 %0, {%1, %1};" : "=l"(r) : "f"(x));
    return r;
}
__device__ __forceinline__ void fma2(unsigned long long &d, unsigned long long a, unsigned long long b) {
    asm("fma.rn.f32x2 %0, %1, %2, %0;" : "+l"(d) : "l"(a), "l"(b));
}
__device__ __forceinline__ void cp16(float* dst, const float* src) {
    unsigned s = (unsigned)__cvta_generic_to_shared(dst);
    asm volatile("cp.async.cg.shared.global [%0], [%1], 16;" :: "r"(s), "l"(src));
}
#define CP_COMMIT() asm volatile("cp.async.commit_group;")
#define CP_WAIT0()  asm volatile("cp.async.wait_group 0;")

__global__ void __launch_bounds__(NTHREADS, 1)
attn_fused(const float* __restrict__ z2d, const float* __restrict__ t2d,
           const float* __restrict__ bo, float* __restrict__ out)
{
    extern __shared__ float sm[];
    float* zsT = sm;                       // [CIN][ZST]  transposed z tile
    float* Us  = sm + CIN*ZST;             // [TILE][UST] U, later zbar (in place)
    float* bufA = Us + TILE*UST;           // double-buffered weight chunks
    float* bufB = bufA + CHUNK_FLOATS;

    const int tid = threadIdx.x;
    const int p0  = blockIdx.x * TILE;

    // ---- load z tile, transposed ----
    {
        const float* zsrc = z2d + (long)p0 * CIN;
        #pragma unroll
        for (int i = 0; i < TILE*CIN/NTHREADS; i++) {
            int idx = tid + i*NTHREADS;
            int px = idx >> 7, c = idx & 127;
            zsT[c*ZST + px] = zsrc[idx];
        }
    }
    // prefetch M chunk 0 (overlaps nothing yet, but starts early)
    cp16(bufA + tid*4, g_Mcat + tid*4);
    cp16(bufA + tid*4 + 2048, g_Mcat + tid*4 + 2048);
    CP_COMMIT();

    const int pixgrp = tid >> 6;   // 0..7 -> 8 pixels each
    const int lsub   = tid & 63;   // column-pair owner

    // ---- phase 1: U[64][512] = Z[64][128] @ Mcat[128][512] ----
    unsigned long long acc[32];    // [px 8][head 4] f32x2 pairs at o = k*128 + 2*lsub
    #pragma unroll
    for (int i = 0; i < 32; i++) acc[i] = 0ull;

    for (int c = 0; c < 16; c++) {          // 16 chunks of 8 k-rows
        CP_WAIT0();
        __syncthreads();                     // chunk c resident; prev half free; zsT visible
        float* bufh = (c & 1) ? bufB : bufA;
        if (c < 15) {
            float* nxt = (c & 1) ? bufA : bufB;
            const float* src = g_Mcat + (c+1)*CHUNK_FLOATS;
            cp16(nxt + tid*4, src + tid*4);
            cp16(nxt + tid*4 + 2048, src + tid*4 + 2048);
            CP_COMMIT();
        }
        #pragma unroll
        for (int kk = 0; kk < 8; kk++) {
            const float* zrow = zsT + (c*8+kk)*ZST + pixgrp*8;
            float4 za  = *(const float4*)(zrow);
            float4 zbv = *(const float4*)(zrow + 4);
            unsigned long long zz[8];
            zz[0]=pack2(za.x);  zz[1]=pack2(za.y);  zz[2]=pack2(za.z);  zz[3]=pack2(za.w);
            zz[4]=pack2(zbv.x); zz[5]=pack2(zbv.y); zz[6]=pack2(zbv.z); zz[7]=pack2(zbv.w);
            const float* mrow = bufh + kk*OD + 2*lsub;
            #pragma unroll
            for (int k = 0; k < 4; k++) {
                unsigned long long mv = *(const unsigned long long*)(mrow + k*128);
                #pragma unroll
                for (int px = 0; px < 8; px++)
                    fma2(acc[px*4 + k], zz[px], mv);
            }
        }
    }
    #pragma unroll
    for (int px = 0; px < 8; px++) {
        float* urow = Us + (pixgrp*8 + px)*UST + 2*lsub;
        #pragma unroll
        for (int k = 0; k < 4; k++)
            *(unsigned long long*)(urow + k*128) = acc[px*4 + k];
    }
    __syncthreads();   // U complete; all phase-1 reads of bufA/bufB done

    // prefetch P chunk 0 into bufA — rides under all of phase 2
    cp16(bufA + tid*4, g_Pcat + tid*4);
    cp16(bufA + tid*4 + 2048, g_Pcat + tid*4 + 2048);
    CP_COMMIT();

    // ---- phase 2: scores (U . z_t), softmax over t, zbar -> Us (in place) ----
    {
        const int lane = tid & 31;
        const int pix  = (tid >> 5) * 4 + (lane & 3);  // conflict-free LDS mapping
        const int sub  = lane >> 2;                    // 0..7, in-warp reduction group
        const int cb   = sub * 16;
        const float* zt0 = t2d + (long)(p0 + pix) * CIN + cb;

        float s[NT][NH];
        #pragma unroll
        for (int t = 0; t < NT; t++)
            #pragma unroll
            for (int h = 0; h < NH; h++) s[t][h] = 0.f;

        #pragma unroll
        for (int q4 = 0; q4 < 4; q4++) {
            float4 zl[NT];
            #pragma unroll
            for (int t = 0; t < NT; t++)
                zl[t] = *(const float4*)(zt0 + (long)t * NPIX * CIN + q4*4);
            #pragma unroll
            for (int h = 0; h < NH; h++) {
                float4 u = *(const float4*)(Us + pix*UST + h*128 + cb + q4*4);
                #pragma unroll
                for (int t = 0; t < NT; t++)
                    s[t][h] += u.x*zl[t].x + u.y*zl[t].y + u.z*zl[t].z + u.w*zl[t].w;
            }
        }
        #pragma unroll
        for (int t = 0; t < NT; t++)
            #pragma unroll
            for (int h = 0; h < NH; h++) {
                float p = s[t][h];
                p += __shfl_xor_sync(0xffffffffu, p, 4);
                p += __shfl_xor_sync(0xffffffffu, p, 8);
                p += __shfl_xor_sync(0xffffffffu, p, 16);
                s[t][h] = p * SCALE;
            }
        float w[NT][NH];
        #pragma unroll
        for (int h = 0; h < NH; h++) {
            float m = fmaxf(fmaxf(s[0][h], s[1][h]), fmaxf(s[2][h], s[3][h]));
            float e0 = __expf(s[0][h]-m), e1 = __expf(s[1][h]-m);
            float e2 = __expf(s[2][h]-m), e3 = __expf(s[3][h]-m);
            float inv = 1.f / (e0+e1+e2+e3);
            w[0][h]=e0*inv; w[1][h]=e1*inv; w[2][h]=e2*inv; w[3][h]=e3*inv;
        }
        float zb[NH][16];
        #pragma unroll
        for (int h = 0; h < NH; h++)
            #pragma unroll
            for (int q = 0; q < 16; q++) zb[h][q] = 0.f;
        #pragma unroll
        for (int t = 0; t < NT; t++) {
            const float* ztp = zt0 + (long)t * NPIX * CIN;   // L1 hit (second read)
            float4 zl[4];
            #pragma unroll
            for (int q4 = 0; q4 < 4; q4++) zl[q4] = *(const float4*)(ztp + q4*4);
            #pragma unroll
            for (int h = 0; h < NH; h++) {
                float wv = w[t][h];
                #pragma unroll
                for (int q4 = 0; q4 < 4; q4++) {
                    zb[h][q4*4+0] = fmaf(wv, zl[q4].x, zb[h][q4*4+0]);
                    zb[h][q4*4+1] = fmaf(wv, zl[q4].y, zb[h][q4*4+1]);
                    zb[h][q4*4+2] = fmaf(wv, zl[q4].z, zb[h][q4*4+2]);
                    zb[h][q4*4+3] = fmaf(wv, zl[q4].w, zb[h][q4*4+3]);
                }
            }
        }
        #pragma unroll
        for (int h = 0; h < NH; h++) {
            float* urow = Us + pix*UST + h*128 + cb;
            #pragma unroll
            for (int q4 = 0; q4 < 4; q4++)
                *(float4*)(urow + q4*4) = make_float4(zb[h][q4*4+0], zb[h][q4*4+1],
                                                      zb[h][q4*4+2], zb[h][q4*4+3]);
        }
    }

    // ---- phase 3: out[64][128] = zbar[64][512] @ Pcat[512][128] + bo ----
    {
        unsigned long long oacc[8];
        unsigned long long bo2 = *(const unsigned long long*)(bo + 2*lsub);
        #pragma unroll
        for (int px = 0; px < 8; px++) oacc[px] = bo2;

        for (int c = 0; c < 16; c++) {      // 16 chunks of 32 P-rows
            CP_WAIT0();
            __syncthreads();                 // chunk c resident; zbar visible (c==0)
            float* bufh = (c & 1) ? bufB : bufA;
            if (c < 15) {
                float* nxt = (c & 1) ? bufA : bufB;
                const float* src = g_Pcat + (c+1)*CHUNK_FLOATS;
                cp16(nxt + tid*4, src + tid*4);
                cp16(nxt + tid*4 + 2048, src + tid*4 + 2048);
                CP_COMMIT();
            }
            const int o0 = c * 32;
            #pragma unroll
            for (int og = 0; og < 8; og++) {
                unsigned long long pm[4];
                #pragma unroll
                for (int r = 0; r < 4; r++)
                    pm[r] = *(const unsigned long long*)(bufh + (og*4+r)*CIN + 2*lsub);
                #pragma unroll
                for (int px = 0; px < 8; px++) {
                    const float4 zq = *(const float4*)(Us + (pixgrp*8+px)*UST + o0 + og*4);
                    fma2(oacc[px], pack2(zq.x), pm[0]);
                    fma2(oacc[px], pack2(zq.y), pm[1]);
                    fma2(oacc[px], pack2(zq.z), pm[2]);
                    fma2(oacc[px], pack2(zq.w), pm[3]);
                }
            }
        }
        #pragma unroll
        for (int px = 0; px < 8; px++) {
            long p = p0 + pixgrp*8 + px;
            *(unsigned long long*)(out + p*CIN + 2*lsub) = oacc[px];
        }
    }
}

extern "C" void kernel_launch(void* const* d_in, const int* in_sizes, int n_in,
                              void* d_out, int out_size) {
    const float* z2d = (const float*)d_in[0];
    const float* t2d = (const float*)d_in[1];
    const float* Wq  = (const float*)d_in[2];
    const float* Wk  = (const float*)d_in[3];
    const float* Wv  = (const float*)d_in[4];
    const float* Wo  = (const float*)d_in[5];
    const float* bo  = (const float*)d_in[6];
    float* out = (float*)d_out;

    precompute_MP<<<(CIN*OD + 255)/256, 256>>>(Wq, Wk, Wv, Wo);

    cudaFuncSetAttribute(attn_fused, cudaFuncAttributeMaxDynamicSharedMemorySize,
                         SMEM_FLOATS * (int)sizeof(float));
    attn_fused<<<NPIX/TILE, NTHREADS, SMEM_FLOATS * sizeof(float)>>>(z2d, t2d, bo, out);
}